// round 14
// baseline (speedup 1.0000x reference)
#include <cuda_runtime.h>
#include <cuda_fp16.h>
#include <math.h>
#include <stdint.h>

#define BATCH 128
#define SEQ   256
#define HID   256
#define MROWS 32768
#define SC2_NBLK 128

// ---------------- scratch (no allocations allowed) ----------------
__device__ __half g_xh  [(size_t)MROWS * 1024];   // x in fp16
__device__ __half g_sth [(size_t)MROWS * 128];    // stages fp16, K padded to 128
__device__ __half g_st1h[(size_t)MROWS * 256];
__device__ __half g_st2h[(size_t)MROWS * 512];
__device__ __half g_st3h[(size_t)MROWS * 1024];
__device__ float  g_u   [(size_t)MROWS * 1024];   // [b][t][1024]
__device__ float  g_utr [(size_t)MROWS * 1024];   // [t][col][b]
__device__ float  g_hc[2][2][HID * BATCH];        // [buf][h/c][k*128+b]
__device__ __half g_w1t[256 * 128];               // se_w1^T fp16 (K pad 128)
__device__ __half g_w2t[512 * 256];               // se_w2^T fp16
__device__ __half g_w3t[1024 * 512];              // se_w3^T fp16
__device__ __half g_uT [1024 * 2048];             // U_all_w^T fp16
__device__ unsigned g_bar_count;
__device__ unsigned g_bar_gen;

// ============================ PTX helpers ==================================
__device__ __forceinline__ uint32_t smem_u32(const void* p) {
    uint32_t a;
    asm("{ .reg .u64 t; cvta.to.shared.u64 t, %1; cvt.u32.u64 %0, t; }"
        : "=r"(a) : "l"(p));
    return a;
}
#define CP_ASYNC16(dst, src) \
    asm volatile("cp.async.cg.shared.global [%0], [%1], 16;" \
                 :: "r"(dst), "l"(src) : "memory")
#define CP_ASYNC_COMMIT() asm volatile("cp.async.commit_group;" ::: "memory")
#define CP_ASYNC_WAIT(n)  asm volatile("cp.async.wait_group %0;" ::"n"(n):"memory")

#define LDMX4(r, a) \
    asm volatile("ldmatrix.sync.aligned.m8n8.x4.shared.b16 {%0,%1,%2,%3}, [%4];" \
        : "=r"((r)[0]), "=r"((r)[1]), "=r"((r)[2]), "=r"((r)[3]) : "r"(a))
#define MMA_F16(d, a, b) \
    asm volatile("mma.sync.aligned.m16n8k16.row.col.f32.f16.f16.f32 " \
        "{%0,%1,%2,%3},{%4,%5,%6,%7},{%8,%9},{%0,%1,%2,%3};" \
        : "+f"((d)[0]), "+f"((d)[1]), "+f"((d)[2]), "+f"((d)[3]) \
        : "r"((a)[0]), "r"((a)[1]), "r"((a)[2]), "r"((a)[3]), \
          "r"((b)[0]), "r"((b)[1]))

__device__ __forceinline__ uint32_t swz128(uint32_t off) {
    return off ^ ((off >> 3) & 0x70);
}
__device__ __forceinline__ uint64_t pk2(float lo, float hi) {
    uint64_t r;
    asm("mov.b64 %0, {%1, %2};" : "=l"(r) : "f"(lo), "f"(hi));
    return r;
}
__device__ __forceinline__ float2 upk2(uint64_t v) {
    float2 f;
    asm("mov.b64 {%0, %1}, %2;" : "=f"(f.x), "=f"(f.y) : "l"(v));
    return f;
}
__device__ __forceinline__ uint64_t ffma2(uint64_t a, uint64_t b, uint64_t c) {
    uint64_t d;
    asm("fma.rn.f32x2 %0, %1, %2, %3;" : "=l"(d) : "l"(a), "l"(b), "l"(c));
    return d;
}

// ================= fp16 mma.sync GEMM: C[M,N] = [A1|A2] @ BT^T =============
#define STAGES 3
#define STG_BYTES 32768
#define HG_SMEM (STAGES * STG_BYTES)

__global__ __launch_bounds__(256, 2)
void hgemm_kernel(const __half* __restrict__ A1, int K1,
                  const __half* __restrict__ A2, int K2,
                  const __half* __restrict__ BT,
                  const float* __restrict__ bias,
                  float* __restrict__ Cf, __half* __restrict__ Ch,
                  int M, int N, int Ktot, int relu)
{
    extern __shared__ char smc[];
    const uint32_t sbase = smem_u32(smc);
    const int tid  = threadIdx.x;
    const int wid  = tid >> 5, lane = tid & 31;
    const int n0   = blockIdx.x * 128;
    const int m0   = blockIdx.y * 128;
    const int NCH  = Ktot >> 6;
    const int wm   = wid & 1;
    const int wn   = wid >> 1;

    float acc[4][4][4];
#pragma unroll
    for (int mt = 0; mt < 4; mt++)
#pragma unroll
        for (int nt = 0; nt < 4; nt++)
#pragma unroll
            for (int q = 0; q < 4; q++) acc[mt][nt][q] = 0.f;

    auto load_chunk = [&](int stage, int k0) {
        uint32_t sA = sbase + stage * STG_BYTES;
        uint32_t sB = sA + 16384;
        const __half* Ak; int kl;
        if (k0 < K1) { Ak = A1 + k0; kl = K1; }
        else         { Ak = A2 + (k0 - K1); kl = K2; }
#pragma unroll
        for (int q = 0; q < 4; q++) {
            int v = tid + 256 * q;
            int r = v >> 3, c = (v & 7) << 4;
            CP_ASYNC16(sA + swz128((uint32_t)(r * 128 + c)),
                       (const char*)(Ak + (size_t)(m0 + r) * kl) + c);
        }
#pragma unroll
        for (int q = 0; q < 4; q++) {
            int v = tid + 256 * q;
            int r = v >> 3, c = (v & 7) << 4;
            CP_ASYNC16(sB + swz128((uint32_t)(r * 128 + c)),
                       (const char*)(BT + (size_t)(n0 + r) * Ktot + k0) + c);
        }
        CP_ASYNC_COMMIT();
    };

    load_chunk(0, 0);
    load_chunk(1, 64);

    const int arow_l = (lane & 15);
    const int akb_l  = (lane >> 4) << 4;
    const int brow_l = (lane & 7);
    const int bqb_l  = (lane >> 3) << 4;

    for (int i = 0; i < NCH; i++) {
        if (i < NCH - 1) { CP_ASYNC_WAIT(1); }
        else             { CP_ASYNC_WAIT(0); }
        __syncthreads();

        const int j = i + STAGES - 1;
        if (j < NCH) load_chunk(j % STAGES, j * 64);

        uint32_t sA = sbase + (i % STAGES) * STG_BYTES;
        uint32_t sB = sA + 16384;

#pragma unroll
        for (int s32 = 0; s32 < 2; s32++) {
            uint32_t bfr[4][4];
#pragma unroll
            for (int nt = 0; nt < 4; nt++) {
                int row = wn * 32 + nt * 8 + brow_l;
                LDMX4(bfr[nt], sB + swz128((uint32_t)(row * 128 + s32 * 64 + bqb_l)));
            }
#pragma unroll
            for (int kh = 0; kh < 2; kh++) {
#pragma unroll
                for (int mt = 0; mt < 4; mt++) {
                    uint32_t afr[4];
                    int row = wm * 64 + mt * 16 + arow_l;
                    LDMX4(afr, sA + swz128((uint32_t)(row * 128 + s32 * 64 + kh * 32 + akb_l)));
#pragma unroll
                    for (int nt = 0; nt < 4; nt++)
                        MMA_F16(acc[mt][nt], afr, &bfr[nt][kh * 2]);
                }
            }
        }
        __syncthreads();
    }

    const int mbase = m0 + wm * 64;
    const int nbase = n0 + wn * 32;
    const int cc = (lane & 3) * 2;
    const int rr = lane >> 2;
    float bx[4], by[4];
#pragma unroll
    for (int nt = 0; nt < 4; nt++) {
        bx[nt] = bias[nbase + nt * 8 + cc];
        by[nt] = bias[nbase + nt * 8 + cc + 1];
    }
#pragma unroll
    for (int mt = 0; mt < 4; mt++) {
        int r0 = mbase + mt * 16 + rr;
#pragma unroll
        for (int nt = 0; nt < 4; nt++) {
            int c0 = nbase + nt * 8 + cc;
            float v0 = acc[mt][nt][0] + bx[nt];
            float v1 = acc[mt][nt][1] + by[nt];
            float v2 = acc[mt][nt][2] + bx[nt];
            float v3 = acc[mt][nt][3] + by[nt];
            if (relu) {
                v0 = fmaxf(v0, 0.f); v1 = fmaxf(v1, 0.f);
                v2 = fmaxf(v2, 0.f); v3 = fmaxf(v3, 0.f);
            }
            if (Ch) {
                *(__half2*)(Ch + (size_t)r0 * N + c0) = __floats2half2_rn(v0, v1);
                *(__half2*)(Ch + (size_t)(r0 + 8) * N + c0) = __floats2half2_rn(v2, v3);
            } else {
                *(float2*)(Cf + (size_t)r0 * N + c0) = make_float2(v0, v1);
                *(float2*)(Cf + (size_t)(r0 + 8) * N + c0) = make_float2(v2, v3);
            }
        }
    }
}

// ---------------- weight transposes (fp16 out) + barrier init --------------
__global__ void wtrans_kernel(const float* __restrict__ w2,
                              const float* __restrict__ w3,
                              const float* __restrict__ uw,
                              const float* __restrict__ w1)
{
    if (blockIdx.x == 0 && blockIdx.y == 0 && blockIdx.z == 0 &&
        threadIdx.x == 0 && threadIdx.y == 0) {
        g_bar_count = 0u;
        g_bar_gen = 0u;
    }
    __shared__ float t[32][33];
    const int tx = threadIdx.x, ty = threadIdx.y;

    if (blockIdx.z == 3) {
        if ((int)blockIdx.x * 32 >= 256 || (int)blockIdx.y * 32 >= 128) return;
#pragma unroll
        for (int i = 0; i < 4; i++) {
            int r = blockIdx.y * 32 + ty + i * 8;
            int c = blockIdx.x * 32 + tx;
            t[ty + i * 8][tx] = (r < 67) ? w1[(size_t)r * 256 + c] : 0.f;
        }
        __syncthreads();
#pragma unroll
        for (int i = 0; i < 4; i++) {
            int c = blockIdx.x * 32 + ty + i * 8;
            int r = blockIdx.y * 32 + tx;
            g_w1t[(size_t)c * 128 + r] = __float2half_rn(t[tx][ty + i * 8]);
        }
        return;
    }

    const float* in; __half* out; int R, C;
    if (blockIdx.z == 0)      { in = w2; out = g_w2t; R = 256;  C = 512;  }
    else if (blockIdx.z == 1) { in = w3; out = g_w3t; R = 512;  C = 1024; }
    else                      { in = uw; out = g_uT;  R = 2048; C = 1024; }
    if ((int)blockIdx.x * 32 >= C || (int)blockIdx.y * 32 >= R) return;
#pragma unroll
    for (int i = 0; i < 4; i++) {
        int r = blockIdx.y * 32 + ty + i * 8;
        int c = blockIdx.x * 32 + tx;
        t[ty + i * 8][tx] = in[(size_t)r * C + c];
    }
    __syncthreads();
#pragma unroll
    for (int i = 0; i < 4; i++) {
        int c = blockIdx.x * 32 + ty + i * 8;
        int r = blockIdx.y * 32 + tx;
        out[(size_t)c * R + r] = __float2half_rn(t[tx][ty + i * 8]);
    }
}

// ---------------- input conversions ----------------------------------------
__global__ void convx_kernel(const float* __restrict__ x)
{
    size_t i = ((size_t)blockIdx.x * 512 + threadIdx.x) * 4;
    float4 v = *(const float4*)(x + i);
    *(__half2*)(&g_xh[i])     = __floats2half2_rn(v.x, v.y);
    *(__half2*)(&g_xh[i + 2]) = __floats2half2_rn(v.z, v.w);
}
// stages -> fp16 (K pad 128)  +  out init to cls bias (cls fused into scan)
__global__ void convs_kernel(const float* __restrict__ s,
                             const float* __restrict__ cls_b,
                             float* __restrict__ out)
{
    int idx = blockIdx.x * 256 + threadIdx.x;
    int m = idx >> 7, k = idx & 127;
    float v = (k < 67) ? s[(size_t)m * 67 + k] : 0.f;
    g_sth[idx] = __float2half_rn(v);
    if (idx < MROWS) out[idx] = cls_b[0];
}

__device__ __forceinline__ void grid_barrier(unsigned gen)
{
    __syncthreads();
    if (threadIdx.x == 0) {
        __threadfence();
        unsigned arrived = atomicAdd(&g_bar_count, 1u) + 1u;
        if (arrived == gen * SC2_NBLK) {
            __threadfence();
            *(volatile unsigned*)&g_bar_gen = gen;
        } else {
            while (*(volatile unsigned*)&g_bar_gen < gen) { __nanosleep(32); }
        }
        __threadfence();
    }
    __syncthreads();
}

__device__ __forceinline__ float sigf(float x) { return 1.f / (1.f + __expf(-x)); }

// ================= persistent TLSTM scan (R8/R13 core + fused cls) =========
#define S2_WOFF 0                 // Wsm2: uint64 [256*4*5]   = 40960 B
#define S2_POFF 40960             // P:    float  [16*4*5*64] = 81920 B (also transpose tiles)
#define S2_BOFF 122880            // Bi:   float  [20]
#define S2_SMEM 123008

__global__ __launch_bounds__(512, 1) void scan2_kernel(
    const float* __restrict__ u,
    const float* __restrict__ ts,
    const float* __restrict__ W_all, const float* __restrict__ W_all_b,
    const float* __restrict__ W_d,   const float* __restrict__ W_d_b,
    const float* __restrict__ cls_w,
    float* __restrict__ out,
    float* __restrict__ feat)
{
    extern __shared__ char smc[];
    uint64_t* Wsm = (uint64_t*)(smc + S2_WOFF);
    float*    P   = (float*)(smc + S2_POFF);
    float*    Bi  = (float*)(smc + S2_BOFF);

    const int tid    = threadIdx.x;
    const int bh     = blockIdx.x & 1;
    const int j0     = (blockIdx.x >> 1) * 4;
    const int b_base = bh * 64;

    // ---- stage weights (once), duplicated into f32x2 pairs ----
    for (int idx = tid; idx < 5120; idx += 512) {
        int k = idx / 20, r = idx % 20;
        int j = r / 5, g = r % 5;
        float v = (g < 4) ? W_all[k * 1024 + g * 256 + j0 + j]
                          : W_d[k * 256 + j0 + j];
        Wsm[(k * 4 + j) * 5 + g] = pk2(v, v);
    }
    if (tid < 20) {
        int j = tid / 5, g = tid % 5;
        Bi[tid] = (g < 4) ? W_all_b[g * 256 + j0 + j] : W_d_b[j0 + j];
    }
    __syncthreads();

    // ---- u transpose: u[(b*SEQ+t)*1024+n] -> g_utr[(t*1024+n)*128+b] ----
    {
        const int tx = tid & 31, ty = (tid >> 5) & 7, slot = tid >> 8;
        float* T = P + slot * (32 * 33);
        for (int it = 0; it < 128; it++) {
            int tileIdx = blockIdx.x * 256 + it * 2 + slot;
            int nt = tileIdx & 31;
            int t  = (tileIdx >> 5) & 255;
            int bt = tileIdx >> 13;
#pragma unroll
            for (int i = 0; i < 4; i++)
                T[(ty + i * 8) * 33 + tx] =
                    u[((size_t)((bt * 32 + ty + i * 8) * SEQ + t)) * 1024 + nt * 32 + tx];
            __syncthreads();
#pragma unroll
            for (int i = 0; i < 4; i++)
                g_utr[((size_t)t * 1024 + nt * 32 + ty + i * 8) * 128 + bt * 32 + tx] =
                    T[tx * 33 + ty + i * 8];
            __syncthreads();
        }
    }

    // zero h0/c0 (parity-0 buffers)
    {
        float* hc0 = &g_hc[0][0][0];
        for (int idx = blockIdx.x * 512 + tid; idx < 2 * HID * BATCH;
             idx += SC2_NBLK * 512)
            hc0[idx] = 0.f;
    }
    grid_barrier(1);

    const int warp = tid >> 5, lane = tid & 31;
    const int jp = lane >> 4;
    const int bq = lane & 15;
    const int b  = b_base + bq * 4;
    const int kbeg = warp * 16;
    const int rjj = tid >> 6, rbl = tid & 63;          // reduction role
    const int rjg = j0 + rjj, rbg = b_base + rbl;

    // hoist per-thread constants for the reduction role
    float bi0 = 0.f, bi1 = 0.f, bi2 = 0.f, bi3 = 0.f, bi4 = 0.f, cwr = 0.f;
    if (tid < 256) {
        bi0 = Bi[rjj * 5 + 0]; bi1 = Bi[rjj * 5 + 1];
        bi2 = Bi[rjj * 5 + 2]; bi3 = Bi[rjj * 5 + 3];
        bi4 = Bi[rjj * 5 + 4];
        cwr = cls_w[rjg];
    }

    for (int t = 0; t < SEQ; t++) {
        const float* hT = &g_hc[t & 1][0][0];
        const float* cT = &g_hc[t & 1][1][0];

        // prefetch pointwise operands (independent of h/c) — overlaps FMA
        float pu0 = 0.f, pu1 = 0.f, pu2 = 0.f, pu3 = 0.f, ptt = 0.f, pcp = 0.f;
        if (tid < 256) {
            const float* up = g_utr + ((size_t)t * 1024 + rjg) * 128 + rbg;
            pu0 = __ldg(up + 0 * 256 * 128);
            pu1 = __ldg(up + 1 * 256 * 128);
            pu2 = __ldg(up + 2 * 256 * 128);
            pu3 = __ldg(up + 3 * 256 * 128);
            ptt = __ldg(ts + rbg * SEQ + t);
            pcp = cT[rjg * 128 + rbg];
        }

        uint64_t acc2[2][5][2];
#pragma unroll
        for (int jj = 0; jj < 2; jj++)
#pragma unroll
            for (int g = 0; g < 5; g++) {
                acc2[jj][g][0] = 0ull;
                acc2[jj][g][1] = 0ull;
            }

#pragma unroll 8
        for (int kk = 0; kk < 16; kk++) {
            int k = kbeg + kk;
            float4 h4 = *(const float4*)(hT + k * 128 + b);
            float4 c4 = *(const float4*)(cT + k * 128 + b);
            uint64_t hp0 = pk2(h4.x, h4.y), hp1 = pk2(h4.z, h4.w);
            uint64_t cp0 = pk2(c4.x, c4.y), cp1 = pk2(c4.z, c4.w);
#pragma unroll
            for (int jj = 0; jj < 2; jj++) {
                const uint64_t* wr = Wsm + ((size_t)(k * 4 + jp * 2 + jj)) * 5;
                uint64_t w0 = wr[0], w1 = wr[1], w2 = wr[2], w3 = wr[3], w4 = wr[4];
                acc2[jj][0][0] = ffma2(hp0, w0, acc2[jj][0][0]);
                acc2[jj][0][1] = ffma2(hp1, w0, acc2[jj][0][1]);
                acc2[jj][1][0] = ffma2(hp0, w1, acc2[jj][1][0]);
                acc2[jj][1][1] = ffma2(hp1, w1, acc2[jj][1][1]);
                acc2[jj][2][0] = ffma2(hp0, w2, acc2[jj][2][0]);
                acc2[jj][2][1] = ffma2(hp1, w2, acc2[jj][2][1]);
                acc2[jj][3][0] = ffma2(hp0, w3, acc2[jj][3][0]);
                acc2[jj][3][1] = ffma2(hp1, w3, acc2[jj][3][1]);
                acc2[jj][4][0] = ffma2(cp0, w4, acc2[jj][4][0]);
                acc2[jj][4][1] = ffma2(cp1, w4, acc2[jj][4][1]);
            }
        }

#pragma unroll
        for (int jj = 0; jj < 2; jj++)
#pragma unroll
            for (int g = 0; g < 5; g++) {
                float2 lo = upk2(acc2[jj][g][0]);
                float2 hi = upk2(acc2[jj][g][1]);
                *(float4*)&P[((warp * 4 + jp * 2 + jj) * 5 + g) * 64 + bq * 4] =
                    make_float4(lo.x, lo.y, hi.x, hi.y);
            }
        __syncthreads();

        if (tid < 256) {
            float s0 = bi0, s1 = bi1, s2 = bi2, s3 = bi3, s4 = bi4;
#pragma unroll
            for (int q = 0; q < 16; q++) {
                const float* Pq = &P[((q * 4 + rjj) * 5) * 64 + rbl];
                s0 += Pq[0 * 64];
                s1 += Pq[1 * 64];
                s2 += Pq[2 * 64];
                s3 += Pq[3 * 64];
                s4 += Pq[4 * 64];
            }
            float f  = sigf(s0 + pu0);
            float ii = sigf(s1 + pu1);
            float o  = sigf(s2 + pu2);
            float ct = sigf(s3 + pu3);
            float d  = tanhf(s4);
            float c_adj = (pcp - d) + d * ptt;
            float cn = f * c_adj + ii * ct;
            float hn = o * tanhf(cn);
            g_hc[(t + 1) & 1][0][rjg * 128 + rbg] = hn;
            g_hc[(t + 1) & 1][1][rjg * 128 + rbg] = cn;
            feat[((size_t)rbg * SEQ + t) * HID + rjg] = hn;
            atomicAdd(&out[rbg * SEQ + t], hn * cwr);   // fused classifier
        }
        grid_barrier((unsigned)(t + 2));
    }
}

// ---------------------------------------------------------------------------
extern "C" void kernel_launch(void* const* d_in, const int* in_sizes, int n_in,
                              void* d_out, int out_size)
{
    const float* x       = (const float*)d_in[0];
    const float* stages  = (const float*)d_in[1];
    const float* tsmp    = (const float*)d_in[2];
    const float* se_w1   = (const float*)d_in[3];
    const float* se_b1   = (const float*)d_in[4];
    const float* se_w2   = (const float*)d_in[5];
    const float* se_b2   = (const float*)d_in[6];
    const float* se_w3   = (const float*)d_in[7];
    const float* se_b3   = (const float*)d_in[8];
    const float* W_all_w = (const float*)d_in[9];
    const float* W_all_b = (const float*)d_in[10];
    const float* U_all_w = (const float*)d_in[11];
    const float* U_all_b = (const float*)d_in[12];
    const float* W_d_w   = (const float*)d_in[13];
    const float* W_d_b   = (const float*)d_in[14];
    const float* cls_w   = (const float*)d_in[15];
    const float* cls_b   = (const float*)d_in[16];

    float* out  = (float*)d_out;
    float* feat = out + MROWS;

    void *p_sth, *p_st1, *p_st2, *p_st3, *p_u, *p_w1t, *p_w2t, *p_w3t, *p_uT, *p_xh;
    cudaGetSymbolAddress(&p_sth, g_sth);
    cudaGetSymbolAddress(&p_st1, g_st1h);
    cudaGetSymbolAddress(&p_st2, g_st2h);
    cudaGetSymbolAddress(&p_st3, g_st3h);
    cudaGetSymbolAddress(&p_u,   g_u);
    cudaGetSymbolAddress(&p_w1t, g_w1t);
    cudaGetSymbolAddress(&p_w2t, g_w2t);
    cudaGetSymbolAddress(&p_w3t, g_w3t);
    cudaGetSymbolAddress(&p_uT,  g_uT);
    cudaGetSymbolAddress(&p_xh,  g_xh);
    __half* sth  = (__half*)p_sth;
    __half* st1h = (__half*)p_st1;
    __half* st2h = (__half*)p_st2;
    __half* st3h = (__half*)p_st3;
    float*  u    = (float*)p_u;
    __half* w1t  = (__half*)p_w1t;
    __half* w2t  = (__half*)p_w2t;
    __half* w3t  = (__half*)p_w3t;
    __half* uT   = (__half*)p_uT;
    __half* xh   = (__half*)p_xh;

    cudaFuncSetAttribute(hgemm_kernel,
                         cudaFuncAttributeMaxDynamicSharedMemorySize, HG_SMEM);
    cudaFuncSetAttribute(scan2_kernel,
                         cudaFuncAttributeMaxDynamicSharedMemorySize, S2_SMEM);

    // 1. weight transposes (fp16) + barrier init
    wtrans_kernel<<<dim3(32, 64, 4), dim3(32, 8)>>>(se_w2, se_w3, U_all_w, se_w1);
    // 2. x/stages -> fp16; out init to cls bias
    convx_kernel<<<16384, 512>>>(x);
    convs_kernel<<<16384, 256>>>(stages, cls_b, out);
    // 3. se1: fp16 mma, K=128 (padded)
    hgemm_kernel<<<dim3(2, 256), 256, HG_SMEM>>>(
        sth, 128, sth, 128, w1t, se_b1, nullptr, st1h, MROWS, 256, 128, 1);
    // 4. se2: K=256
    hgemm_kernel<<<dim3(4, 256), 256, HG_SMEM>>>(
        st1h, 256, st1h, 256, w2t, se_b2, nullptr, st2h, MROWS, 512, 256, 1);
    // 5. se3: K=512
    hgemm_kernel<<<dim3(8, 256), 256, HG_SMEM>>>(
        st2h, 512, st2h, 512, w3t, se_b3, nullptr, st3h, MROWS, 1024, 512, 1);
    // 6. uproj fused: [x | st3] K=2048, fp32 out
    hgemm_kernel<<<dim3(8, 256), 256, HG_SMEM>>>(
        xh, 1024, st3h, 1024, uT, U_all_b, u, nullptr, MROWS, 1024, 2048, 0);
    // 7. persistent scan (u transpose prologue, coalesced reads, fused cls)
    scan2_kernel<<<SC2_NBLK, 512, S2_SMEM>>>(u, tsmp, W_all_w, W_all_b,
                                             W_d_w, W_d_b, cls_w, out, feat);
}

// round 15
// speedup vs baseline: 1.6022x; 1.6022x over previous
#include <cuda_runtime.h>
#include <cuda_fp16.h>
#include <math.h>
#include <stdint.h>

#define BATCH 128
#define SEQ   256
#define HID   256
#define MROWS 32768
#define SC2_NBLK 128

// ---------------- scratch (no allocations allowed) ----------------
__device__ __half g_xh  [(size_t)MROWS * 1024];   // x in fp16
__device__ __half g_sth [(size_t)MROWS * 128];    // stages fp16, K padded to 128
__device__ __half g_st1h[(size_t)MROWS * 256];
__device__ __half g_st2h[(size_t)MROWS * 512];
__device__ __half g_st3h[(size_t)MROWS * 1024];
__device__ float  g_u   [(size_t)MROWS * 1024];   // [b][t][1024]
__device__ float  g_utr [(size_t)MROWS * 1024];   // [t][col][b]
__device__ float  g_hc[2][2][HID * BATCH];        // [buf][h/c][k*128+b]
__device__ __half g_w1t[256 * 128];               // se_w1^T fp16 (K pad 128)
__device__ __half g_w2t[512 * 256];               // se_w2^T fp16
__device__ __half g_w3t[1024 * 512];              // se_w3^T fp16
__device__ __half g_uT [1024 * 2048];             // U_all_w^T fp16
__device__ unsigned g_bar_count;
__device__ unsigned g_bar_gen;

// ============================ PTX helpers ==================================
__device__ __forceinline__ uint32_t smem_u32(const void* p) {
    uint32_t a;
    asm("{ .reg .u64 t; cvta.to.shared.u64 t, %1; cvt.u32.u64 %0, t; }"
        : "=r"(a) : "l"(p));
    return a;
}
#define CP_ASYNC16(dst, src) \
    asm volatile("cp.async.cg.shared.global [%0], [%1], 16;" \
                 :: "r"(dst), "l"(src) : "memory")
#define CP_ASYNC_COMMIT() asm volatile("cp.async.commit_group;" ::: "memory")
#define CP_ASYNC_WAIT(n)  asm volatile("cp.async.wait_group %0;" ::"n"(n):"memory")

#define LDMX4(r, a) \
    asm volatile("ldmatrix.sync.aligned.m8n8.x4.shared.b16 {%0,%1,%2,%3}, [%4];" \
        : "=r"((r)[0]), "=r"((r)[1]), "=r"((r)[2]), "=r"((r)[3]) : "r"(a))
#define MMA_F16(d, a, b) \
    asm volatile("mma.sync.aligned.m16n8k16.row.col.f32.f16.f16.f32 " \
        "{%0,%1,%2,%3},{%4,%5,%6,%7},{%8,%9},{%0,%1,%2,%3};" \
        : "+f"((d)[0]), "+f"((d)[1]), "+f"((d)[2]), "+f"((d)[3]) \
        : "r"((a)[0]), "r"((a)[1]), "r"((a)[2]), "r"((a)[3]), \
          "r"((b)[0]), "r"((b)[1]))

__device__ __forceinline__ uint32_t swz128(uint32_t off) {
    return off ^ ((off >> 3) & 0x70);
}
__device__ __forceinline__ uint64_t pk2(float lo, float hi) {
    uint64_t r;
    asm("mov.b64 %0, {%1, %2};" : "=l"(r) : "f"(lo), "f"(hi));
    return r;
}
__device__ __forceinline__ float2 upk2(uint64_t v) {
    float2 f;
    asm("mov.b64 {%0, %1}, %2;" : "=f"(f.x), "=f"(f.y) : "l"(v));
    return f;
}
__device__ __forceinline__ uint64_t ffma2(uint64_t a, uint64_t b, uint64_t c) {
    uint64_t d;
    asm("fma.rn.f32x2 %0, %1, %2, %3;" : "=l"(d) : "l"(a), "l"(b), "l"(c));
    return d;
}

// ================= fp16 mma.sync GEMM: C[M,N] = [A1|A2] @ BT^T =============
#define STAGES 3
#define STG_BYTES 32768
#define HG_SMEM (STAGES * STG_BYTES)

__global__ __launch_bounds__(256, 2)
void hgemm_kernel(const __half* __restrict__ A1, int K1,
                  const __half* __restrict__ A2, int K2,
                  const __half* __restrict__ BT,
                  const float* __restrict__ bias,
                  float* __restrict__ Cf, __half* __restrict__ Ch,
                  int M, int N, int Ktot, int relu)
{
    extern __shared__ char smc[];
    const uint32_t sbase = smem_u32(smc);
    const int tid  = threadIdx.x;
    const int wid  = tid >> 5, lane = tid & 31;
    const int n0   = blockIdx.x * 128;
    const int m0   = blockIdx.y * 128;
    const int NCH  = Ktot >> 6;
    const int wm   = wid & 1;
    const int wn   = wid >> 1;

    float acc[4][4][4];
#pragma unroll
    for (int mt = 0; mt < 4; mt++)
#pragma unroll
        for (int nt = 0; nt < 4; nt++)
#pragma unroll
            for (int q = 0; q < 4; q++) acc[mt][nt][q] = 0.f;

    auto load_chunk = [&](int stage, int k0) {
        uint32_t sA = sbase + stage * STG_BYTES;
        uint32_t sB = sA + 16384;
        const __half* Ak; int kl;
        if (k0 < K1) { Ak = A1 + k0; kl = K1; }
        else         { Ak = A2 + (k0 - K1); kl = K2; }
#pragma unroll
        for (int q = 0; q < 4; q++) {
            int v = tid + 256 * q;
            int r = v >> 3, c = (v & 7) << 4;
            CP_ASYNC16(sA + swz128((uint32_t)(r * 128 + c)),
                       (const char*)(Ak + (size_t)(m0 + r) * kl) + c);
        }
#pragma unroll
        for (int q = 0; q < 4; q++) {
            int v = tid + 256 * q;
            int r = v >> 3, c = (v & 7) << 4;
            CP_ASYNC16(sB + swz128((uint32_t)(r * 128 + c)),
                       (const char*)(BT + (size_t)(n0 + r) * Ktot + k0) + c);
        }
        CP_ASYNC_COMMIT();
    };

    load_chunk(0, 0);
    load_chunk(1, 64);

    const int arow_l = (lane & 15);
    const int akb_l  = (lane >> 4) << 4;
    const int brow_l = (lane & 7);
    const int bqb_l  = (lane >> 3) << 4;

    for (int i = 0; i < NCH; i++) {
        if (i < NCH - 1) { CP_ASYNC_WAIT(1); }
        else             { CP_ASYNC_WAIT(0); }
        __syncthreads();

        const int j = i + STAGES - 1;
        if (j < NCH) load_chunk(j % STAGES, j * 64);

        uint32_t sA = sbase + (i % STAGES) * STG_BYTES;
        uint32_t sB = sA + 16384;

#pragma unroll
        for (int s32 = 0; s32 < 2; s32++) {
            uint32_t bfr[4][4];
#pragma unroll
            for (int nt = 0; nt < 4; nt++) {
                int row = wn * 32 + nt * 8 + brow_l;
                LDMX4(bfr[nt], sB + swz128((uint32_t)(row * 128 + s32 * 64 + bqb_l)));
            }
#pragma unroll
            for (int kh = 0; kh < 2; kh++) {
#pragma unroll
                for (int mt = 0; mt < 4; mt++) {
                    uint32_t afr[4];
                    int row = wm * 64 + mt * 16 + arow_l;
                    LDMX4(afr, sA + swz128((uint32_t)(row * 128 + s32 * 64 + kh * 32 + akb_l)));
#pragma unroll
                    for (int nt = 0; nt < 4; nt++)
                        MMA_F16(acc[mt][nt], afr, &bfr[nt][kh * 2]);
                }
            }
        }
        __syncthreads();
    }

    const int mbase = m0 + wm * 64;
    const int nbase = n0 + wn * 32;
    const int cc = (lane & 3) * 2;
    const int rr = lane >> 2;
    float bx[4], by[4];
#pragma unroll
    for (int nt = 0; nt < 4; nt++) {
        bx[nt] = bias[nbase + nt * 8 + cc];
        by[nt] = bias[nbase + nt * 8 + cc + 1];
    }
#pragma unroll
    for (int mt = 0; mt < 4; mt++) {
        int r0 = mbase + mt * 16 + rr;
#pragma unroll
        for (int nt = 0; nt < 4; nt++) {
            int c0 = nbase + nt * 8 + cc;
            float v0 = acc[mt][nt][0] + bx[nt];
            float v1 = acc[mt][nt][1] + by[nt];
            float v2 = acc[mt][nt][2] + bx[nt];
            float v3 = acc[mt][nt][3] + by[nt];
            if (relu) {
                v0 = fmaxf(v0, 0.f); v1 = fmaxf(v1, 0.f);
                v2 = fmaxf(v2, 0.f); v3 = fmaxf(v3, 0.f);
            }
            if (Ch) {
                *(__half2*)(Ch + (size_t)r0 * N + c0) = __floats2half2_rn(v0, v1);
                *(__half2*)(Ch + (size_t)(r0 + 8) * N + c0) = __floats2half2_rn(v2, v3);
            } else {
                *(float2*)(Cf + (size_t)r0 * N + c0) = make_float2(v0, v1);
                *(float2*)(Cf + (size_t)(r0 + 8) * N + c0) = make_float2(v2, v3);
            }
        }
    }
}

// ---------------- weight transposes (fp16 out) + barrier init --------------
__global__ void wtrans_kernel(const float* __restrict__ w2,
                              const float* __restrict__ w3,
                              const float* __restrict__ uw,
                              const float* __restrict__ w1)
{
    if (blockIdx.x == 0 && blockIdx.y == 0 && blockIdx.z == 0 &&
        threadIdx.x == 0 && threadIdx.y == 0) {
        g_bar_count = 0u;
        g_bar_gen = 0u;
    }
    __shared__ float t[32][33];
    const int tx = threadIdx.x, ty = threadIdx.y;

    if (blockIdx.z == 3) {
        if ((int)blockIdx.x * 32 >= 256 || (int)blockIdx.y * 32 >= 128) return;
#pragma unroll
        for (int i = 0; i < 4; i++) {
            int r = blockIdx.y * 32 + ty + i * 8;
            int c = blockIdx.x * 32 + tx;
            t[ty + i * 8][tx] = (r < 67) ? w1[(size_t)r * 256 + c] : 0.f;
        }
        __syncthreads();
#pragma unroll
        for (int i = 0; i < 4; i++) {
            int c = blockIdx.x * 32 + ty + i * 8;
            int r = blockIdx.y * 32 + tx;
            g_w1t[(size_t)c * 128 + r] = __float2half_rn(t[tx][ty + i * 8]);
        }
        return;
    }

    const float* in; __half* out; int R, C;
    if (blockIdx.z == 0)      { in = w2; out = g_w2t; R = 256;  C = 512;  }
    else if (blockIdx.z == 1) { in = w3; out = g_w3t; R = 512;  C = 1024; }
    else                      { in = uw; out = g_uT;  R = 2048; C = 1024; }
    if ((int)blockIdx.x * 32 >= C || (int)blockIdx.y * 32 >= R) return;
#pragma unroll
    for (int i = 0; i < 4; i++) {
        int r = blockIdx.y * 32 + ty + i * 8;
        int c = blockIdx.x * 32 + tx;
        t[ty + i * 8][tx] = in[(size_t)r * C + c];
    }
    __syncthreads();
#pragma unroll
    for (int i = 0; i < 4; i++) {
        int c = blockIdx.x * 32 + ty + i * 8;
        int r = blockIdx.y * 32 + tx;
        out[(size_t)c * R + r] = __float2half_rn(t[tx][ty + i * 8]);
    }
}

// ---------------- input conversions ----------------------------------------
__global__ void convx_kernel(const float* __restrict__ x)
{
    size_t i = ((size_t)blockIdx.x * 512 + threadIdx.x) * 4;
    float4 v = *(const float4*)(x + i);
    *(__half2*)(&g_xh[i])     = __floats2half2_rn(v.x, v.y);
    *(__half2*)(&g_xh[i + 2]) = __floats2half2_rn(v.z, v.w);
}
__global__ void convs_kernel(const float* __restrict__ s)
{
    int idx = blockIdx.x * 256 + threadIdx.x;
    int m = idx >> 7, k = idx & 127;
    float v = (k < 67) ? s[(size_t)m * 67 + k] : 0.f;
    g_sth[idx] = __float2half_rn(v);
}

__device__ __forceinline__ void grid_barrier(unsigned gen)
{
    __syncthreads();
    if (threadIdx.x == 0) {
        __threadfence();
        unsigned arrived = atomicAdd(&g_bar_count, 1u) + 1u;
        if (arrived == gen * SC2_NBLK) {
            __threadfence();
            *(volatile unsigned*)&g_bar_gen = gen;
        } else {
            while (*(volatile unsigned*)&g_bar_gen < gen) { __nanosleep(32); }
        }
        __threadfence();
    }
    __syncthreads();
}

__device__ __forceinline__ float sigf(float x) { return 1.f / (1.f + __expf(-x)); }

// ================= persistent TLSTM scan (R13 core; unroll 8 = ONLY delta) =
#define S2_WOFF 0                 // Wsm2: uint64 [256*4*5]   = 40960 B
#define S2_POFF 40960             // P:    float  [16*4*5*64] = 81920 B (also transpose tiles)
#define S2_BOFF 122880            // Bi:   float  [20]
#define S2_SMEM 123008

__global__ __launch_bounds__(512, 1) void scan2_kernel(
    const float* __restrict__ u,
    const float* __restrict__ ts,
    const float* __restrict__ W_all, const float* __restrict__ W_all_b,
    const float* __restrict__ W_d,   const float* __restrict__ W_d_b,
    float* __restrict__ feat)
{
    extern __shared__ char smc[];
    uint64_t* Wsm = (uint64_t*)(smc + S2_WOFF);
    float*    P   = (float*)(smc + S2_POFF);
    float*    Bi  = (float*)(smc + S2_BOFF);

    const int tid    = threadIdx.x;
    const int bh     = blockIdx.x & 1;
    const int j0     = (blockIdx.x >> 1) * 4;
    const int b_base = bh * 64;

    // ---- stage weights (once), duplicated into f32x2 pairs ----
    for (int idx = tid; idx < 5120; idx += 512) {
        int k = idx / 20, r = idx % 20;
        int j = r / 5, g = r % 5;
        float v = (g < 4) ? W_all[k * 1024 + g * 256 + j0 + j]
                          : W_d[k * 256 + j0 + j];
        Wsm[(k * 4 + j) * 5 + g] = pk2(v, v);
    }
    if (tid < 20) {
        int j = tid / 5, g = tid % 5;
        Bi[tid] = (g < 4) ? W_all_b[g * 256 + j0 + j] : W_d_b[j0 + j];
    }
    __syncthreads();

    // ---- u transpose: u[(b*SEQ+t)*1024+n] -> g_utr[(t*1024+n)*128+b] ----
    {
        const int tx = tid & 31, ty = (tid >> 5) & 7, slot = tid >> 8;
        float* T = P + slot * (32 * 33);
        for (int it = 0; it < 128; it++) {
            int tileIdx = blockIdx.x * 256 + it * 2 + slot;
            int nt = tileIdx & 31;
            int t  = (tileIdx >> 5) & 255;
            int bt = tileIdx >> 13;
#pragma unroll
            for (int i = 0; i < 4; i++)
                T[(ty + i * 8) * 33 + tx] =
                    u[((size_t)((bt * 32 + ty + i * 8) * SEQ + t)) * 1024 + nt * 32 + tx];
            __syncthreads();
#pragma unroll
            for (int i = 0; i < 4; i++)
                g_utr[((size_t)t * 1024 + nt * 32 + ty + i * 8) * 128 + bt * 32 + tx] =
                    T[tx * 33 + ty + i * 8];
            __syncthreads();
        }
    }

    // zero h0/c0 (parity-0 buffers)
    {
        float* hc0 = &g_hc[0][0][0];
        for (int idx = blockIdx.x * 512 + tid; idx < 2 * HID * BATCH;
             idx += SC2_NBLK * 512)
            hc0[idx] = 0.f;
    }
    grid_barrier(1);

    const int warp = tid >> 5, lane = tid & 31;
    const int jp = lane >> 4;
    const int bq = lane & 15;
    const int b  = b_base + bq * 4;
    const int kbeg = warp * 16;
    const int rjj = tid >> 6, rbl = tid & 63;          // reduction role
    const int rjg = j0 + rjj, rbg = b_base + rbl;

    for (int t = 0; t < SEQ; t++) {
        const float* hT = &g_hc[t & 1][0][0];
        const float* cT = &g_hc[t & 1][1][0];

        // prefetch pointwise operands (independent of h/c) — overlaps FMA
        float pu0 = 0.f, pu1 = 0.f, pu2 = 0.f, pu3 = 0.f, ptt = 0.f, pcp = 0.f;
        if (tid < 256) {
            const float* up = g_utr + ((size_t)t * 1024 + rjg) * 128 + rbg;
            pu0 = __ldg(up + 0 * 256 * 128);
            pu1 = __ldg(up + 1 * 256 * 128);
            pu2 = __ldg(up + 2 * 256 * 128);
            pu3 = __ldg(up + 3 * 256 * 128);
            ptt = __ldg(ts + rbg * SEQ + t);
            pcp = cT[rjg * 128 + rbg];
        }

        uint64_t acc2[2][5][2];
#pragma unroll
        for (int jj = 0; jj < 2; jj++)
#pragma unroll
            for (int g = 0; g < 5; g++) {
                acc2[jj][g][0] = 0ull;
                acc2[jj][g][1] = 0ull;
            }

#pragma unroll 8
        for (int kk = 0; kk < 16; kk++) {
            int k = kbeg + kk;
            float4 h4 = *(const float4*)(hT + k * 128 + b);
            float4 c4 = *(const float4*)(cT + k * 128 + b);
            uint64_t hp0 = pk2(h4.x, h4.y), hp1 = pk2(h4.z, h4.w);
            uint64_t cp0 = pk2(c4.x, c4.y), cp1 = pk2(c4.z, c4.w);
#pragma unroll
            for (int jj = 0; jj < 2; jj++) {
                const uint64_t* wr = Wsm + ((size_t)(k * 4 + jp * 2 + jj)) * 5;
                uint64_t w0 = wr[0], w1 = wr[1], w2 = wr[2], w3 = wr[3], w4 = wr[4];
                acc2[jj][0][0] = ffma2(hp0, w0, acc2[jj][0][0]);
                acc2[jj][0][1] = ffma2(hp1, w0, acc2[jj][0][1]);
                acc2[jj][1][0] = ffma2(hp0, w1, acc2[jj][1][0]);
                acc2[jj][1][1] = ffma2(hp1, w1, acc2[jj][1][1]);
                acc2[jj][2][0] = ffma2(hp0, w2, acc2[jj][2][0]);
                acc2[jj][2][1] = ffma2(hp1, w2, acc2[jj][2][1]);
                acc2[jj][3][0] = ffma2(hp0, w3, acc2[jj][3][0]);
                acc2[jj][3][1] = ffma2(hp1, w3, acc2[jj][3][1]);
                acc2[jj][4][0] = ffma2(cp0, w4, acc2[jj][4][0]);
                acc2[jj][4][1] = ffma2(cp1, w4, acc2[jj][4][1]);
            }
        }

#pragma unroll
        for (int jj = 0; jj < 2; jj++)
#pragma unroll
            for (int g = 0; g < 5; g++) {
                float2 lo = upk2(acc2[jj][g][0]);
                float2 hi = upk2(acc2[jj][g][1]);
                *(float4*)&P[((warp * 4 + jp * 2 + jj) * 5 + g) * 64 + bq * 4] =
                    make_float4(lo.x, lo.y, hi.x, hi.y);
            }
        __syncthreads();

        if (tid < 256) {
            float s[5];
#pragma unroll
            for (int g = 0; g < 5; g++) s[g] = Bi[rjj * 5 + g];
#pragma unroll
            for (int q = 0; q < 16; q++) {
#pragma unroll
                for (int g = 0; g < 5; g++)
                    s[g] += P[((q * 4 + rjj) * 5 + g) * 64 + rbl];
            }
            float f  = sigf(s[0] + pu0);
            float ii = sigf(s[1] + pu1);
            float o  = sigf(s[2] + pu2);
            float ct = sigf(s[3] + pu3);
            float d  = tanhf(s[4]);
            float c_adj = (pcp - d) + d * ptt;
            float cn = f * c_adj + ii * ct;
            float hn = o * tanhf(cn);
            g_hc[(t + 1) & 1][0][rjg * 128 + rbg] = hn;
            g_hc[(t + 1) & 1][1][rjg * 128 + rbg] = cn;
            feat[((size_t)rbg * SEQ + t) * HID + rjg] = hn;
        }
        grid_barrier((unsigned)(t + 2));
    }
}

// ---------------- classifier ----------------------------------------------
__global__ void cls_kernel(const float* __restrict__ feat,
                           const float* __restrict__ w,
                           const float* __restrict__ bias,
                           float* __restrict__ out)
{
    int lane = threadIdx.x & 31;
    int wrow = (blockIdx.x * blockDim.x + threadIdx.x) >> 5;
    if (wrow >= MROWS) return;
    const float* fr = feat + (size_t)wrow * HID;
    float s = 0.f;
#pragma unroll
    for (int i = 0; i < 8; i++) s += fr[lane + 32 * i] * w[lane + 32 * i];
#pragma unroll
    for (int off = 16; off > 0; off >>= 1)
        s += __shfl_down_sync(0xffffffffu, s, off);
    if (lane == 0) out[wrow] = s + bias[0];
}

// ---------------------------------------------------------------------------
extern "C" void kernel_launch(void* const* d_in, const int* in_sizes, int n_in,
                              void* d_out, int out_size)
{
    const float* x       = (const float*)d_in[0];
    const float* stages  = (const float*)d_in[1];
    const float* tsmp    = (const float*)d_in[2];
    const float* se_w1   = (const float*)d_in[3];
    const float* se_b1   = (const float*)d_in[4];
    const float* se_w2   = (const float*)d_in[5];
    const float* se_b2   = (const float*)d_in[6];
    const float* se_w3   = (const float*)d_in[7];
    const float* se_b3   = (const float*)d_in[8];
    const float* W_all_w = (const float*)d_in[9];
    const float* W_all_b = (const float*)d_in[10];
    const float* U_all_w = (const float*)d_in[11];
    const float* U_all_b = (const float*)d_in[12];
    const float* W_d_w   = (const float*)d_in[13];
    const float* W_d_b   = (const float*)d_in[14];
    const float* cls_w   = (const float*)d_in[15];
    const float* cls_b   = (const float*)d_in[16];

    float* out  = (float*)d_out;
    float* feat = out + MROWS;

    void *p_sth, *p_st1, *p_st2, *p_st3, *p_u, *p_w1t, *p_w2t, *p_w3t, *p_uT, *p_xh;
    cudaGetSymbolAddress(&p_sth, g_sth);
    cudaGetSymbolAddress(&p_st1, g_st1h);
    cudaGetSymbolAddress(&p_st2, g_st2h);
    cudaGetSymbolAddress(&p_st3, g_st3h);
    cudaGetSymbolAddress(&p_u,   g_u);
    cudaGetSymbolAddress(&p_w1t, g_w1t);
    cudaGetSymbolAddress(&p_w2t, g_w2t);
    cudaGetSymbolAddress(&p_w3t, g_w3t);
    cudaGetSymbolAddress(&p_uT,  g_uT);
    cudaGetSymbolAddress(&p_xh,  g_xh);
    __half* sth  = (__half*)p_sth;
    __half* st1h = (__half*)p_st1;
    __half* st2h = (__half*)p_st2;
    __half* st3h = (__half*)p_st3;
    float*  u    = (float*)p_u;
    __half* w1t  = (__half*)p_w1t;
    __half* w2t  = (__half*)p_w2t;
    __half* w3t  = (__half*)p_w3t;
    __half* uT   = (__half*)p_uT;
    __half* xh   = (__half*)p_xh;

    cudaFuncSetAttribute(hgemm_kernel,
                         cudaFuncAttributeMaxDynamicSharedMemorySize, HG_SMEM);
    cudaFuncSetAttribute(scan2_kernel,
                         cudaFuncAttributeMaxDynamicSharedMemorySize, S2_SMEM);

    // 1. weight transposes (fp16) + barrier init
    wtrans_kernel<<<dim3(32, 64, 4), dim3(32, 8)>>>(se_w2, se_w3, U_all_w, se_w1);
    // 2. x/stages -> fp16
    convx_kernel<<<16384, 512>>>(x);
    convs_kernel<<<16384, 256>>>(stages);
    // 3. se1: fp16 mma, K=128 (padded)
    hgemm_kernel<<<dim3(2, 256), 256, HG_SMEM>>>(
        sth, 128, sth, 128, w1t, se_b1, nullptr, st1h, MROWS, 256, 128, 1);
    // 4. se2: K=256
    hgemm_kernel<<<dim3(4, 256), 256, HG_SMEM>>>(
        st1h, 256, st1h, 256, w2t, se_b2, nullptr, st2h, MROWS, 512, 256, 1);
    // 5. se3: K=512
    hgemm_kernel<<<dim3(8, 256), 256, HG_SMEM>>>(
        st2h, 512, st2h, 512, w3t, se_b3, nullptr, st3h, MROWS, 1024, 512, 1);
    // 6. uproj fused: [x | st3] K=2048, fp32 out
    hgemm_kernel<<<dim3(8, 256), 256, HG_SMEM>>>(
        xh, 1024, st3h, 1024, uT, U_all_b, u, nullptr, MROWS, 1024, 2048, 0);
    // 7. persistent scan (R13 structure; kk unroll 8 is the only delta)
    scan2_kernel<<<SC2_NBLK, 512, S2_SMEM>>>(u, tsmp, W_all_w, W_all_b,
                                             W_d_w, W_d_b, feat);
    // 8. classifier
    cls_kernel<<<4096, 256>>>(feat, cls_w, cls_b, out);
}

// round 16
// speedup vs baseline: 1.6683x; 1.0412x over previous
#include <cuda_runtime.h>
#include <cuda_fp16.h>
#include <math.h>
#include <stdint.h>

#define BATCH 128
#define SEQ   256
#define HID   256
#define MROWS 32768
#define SC2_NBLK 128

// ---------------- scratch (no allocations allowed) ----------------
__device__ __half g_xh  [(size_t)MROWS * 1024];   // x in fp16
__device__ __half g_sth [(size_t)MROWS * 128];    // stages fp16, K padded to 128
__device__ __half g_st1h[(size_t)MROWS * 256];
__device__ __half g_st2h[(size_t)MROWS * 512];
__device__ __half g_st3h[(size_t)MROWS * 1024];
__device__ float  g_utr [(size_t)MROWS * 1024];   // [t][col][b]  (uproj writes directly)
__device__ float  g_hc[2][2][HID * BATCH];        // [buf][h/c][k*128+b]
__device__ __half g_w1t[256 * 128];               // se_w1^T fp16 (K pad 128)
__device__ __half g_w2t[512 * 256];               // se_w2^T fp16
__device__ __half g_w3t[1024 * 512];              // se_w3^T fp16
__device__ __half g_uT [1024 * 2048];             // U_all_w^T fp16
__device__ unsigned g_bar_count;
__device__ unsigned g_bar_gen;

// ============================ PTX helpers ==================================
__device__ __forceinline__ uint32_t smem_u32(const void* p) {
    uint32_t a;
    asm("{ .reg .u64 t; cvta.to.shared.u64 t, %1; cvt.u32.u64 %0, t; }"
        : "=r"(a) : "l"(p));
    return a;
}
#define CP_ASYNC16(dst, src) \
    asm volatile("cp.async.cg.shared.global [%0], [%1], 16;" \
                 :: "r"(dst), "l"(src) : "memory")
#define CP_ASYNC_COMMIT() asm volatile("cp.async.commit_group;" ::: "memory")
#define CP_ASYNC_WAIT(n)  asm volatile("cp.async.wait_group %0;" ::"n"(n):"memory")

#define LDMX4(r, a) \
    asm volatile("ldmatrix.sync.aligned.m8n8.x4.shared.b16 {%0,%1,%2,%3}, [%4];" \
        : "=r"((r)[0]), "=r"((r)[1]), "=r"((r)[2]), "=r"((r)[3]) : "r"(a))
#define MMA_F16(d, a, b) \
    asm volatile("mma.sync.aligned.m16n8k16.row.col.f32.f16.f16.f32 " \
        "{%0,%1,%2,%3},{%4,%5,%6,%7},{%8,%9},{%0,%1,%2,%3};" \
        : "+f"((d)[0]), "+f"((d)[1]), "+f"((d)[2]), "+f"((d)[3]) \
        : "r"((a)[0]), "r"((a)[1]), "r"((a)[2]), "r"((a)[3]), \
          "r"((b)[0]), "r"((b)[1]))

__device__ __forceinline__ uint32_t swz128(uint32_t off) {
    return off ^ ((off >> 3) & 0x70);
}
__device__ __forceinline__ uint64_t pk2(float lo, float hi) {
    uint64_t r;
    asm("mov.b64 %0, {%1, %2};" : "=l"(r) : "f"(lo), "f"(hi));
    return r;
}
__device__ __forceinline__ float2 upk2(uint64_t v) {
    float2 f;
    asm("mov.b64 {%0, %1}, %2;" : "=f"(f.x), "=f"(f.y) : "l"(v));
    return f;
}
__device__ __forceinline__ uint64_t ffma2(uint64_t a, uint64_t b, uint64_t c) {
    uint64_t d;
    asm("fma.rn.f32x2 %0, %1, %2, %3;" : "=l"(d) : "l"(a), "l"(b), "l"(c));
    return d;
}

// ================= fp16 mma.sync GEMM: C[M,N] = [A1|A2] @ BT^T =============
#define STAGES 3
#define STG_BYTES 32768
#define HG_SMEM (STAGES * STG_BYTES)

__global__ __launch_bounds__(256, 2)
void hgemm_kernel(const __half* __restrict__ A1, int K1,
                  const __half* __restrict__ A2, int K2,
                  const __half* __restrict__ BT,
                  const float* __restrict__ bias,
                  float* __restrict__ Cf, __half* __restrict__ Ch,
                  int M, int N, int Ktot, int relu)
{
    extern __shared__ char smc[];
    const uint32_t sbase = smem_u32(smc);
    const int tid  = threadIdx.x;
    const int wid  = tid >> 5, lane = tid & 31;
    const int n0   = blockIdx.x * 128;
    const int m0   = blockIdx.y * 128;
    const int NCH  = Ktot >> 6;
    const int wm   = wid & 1;
    const int wn   = wid >> 1;

    float acc[4][4][4];
#pragma unroll
    for (int mt = 0; mt < 4; mt++)
#pragma unroll
        for (int nt = 0; nt < 4; nt++)
#pragma unroll
            for (int q = 0; q < 4; q++) acc[mt][nt][q] = 0.f;

    auto load_chunk = [&](int stage, int k0) {
        uint32_t sA = sbase + stage * STG_BYTES;
        uint32_t sB = sA + 16384;
        const __half* Ak; int kl;
        if (k0 < K1) { Ak = A1 + k0; kl = K1; }
        else         { Ak = A2 + (k0 - K1); kl = K2; }
#pragma unroll
        for (int q = 0; q < 4; q++) {
            int v = tid + 256 * q;
            int r = v >> 3, c = (v & 7) << 4;
            CP_ASYNC16(sA + swz128((uint32_t)(r * 128 + c)),
                       (const char*)(Ak + (size_t)(m0 + r) * kl) + c);
        }
#pragma unroll
        for (int q = 0; q < 4; q++) {
            int v = tid + 256 * q;
            int r = v >> 3, c = (v & 7) << 4;
            CP_ASYNC16(sB + swz128((uint32_t)(r * 128 + c)),
                       (const char*)(BT + (size_t)(n0 + r) * Ktot + k0) + c);
        }
        CP_ASYNC_COMMIT();
    };

    load_chunk(0, 0);
    load_chunk(1, 64);

    const int arow_l = (lane & 15);
    const int akb_l  = (lane >> 4) << 4;
    const int brow_l = (lane & 7);
    const int bqb_l  = (lane >> 3) << 4;

    for (int i = 0; i < NCH; i++) {
        if (i < NCH - 1) { CP_ASYNC_WAIT(1); }
        else             { CP_ASYNC_WAIT(0); }
        __syncthreads();

        const int j = i + STAGES - 1;
        if (j < NCH) load_chunk(j % STAGES, j * 64);

        uint32_t sA = sbase + (i % STAGES) * STG_BYTES;
        uint32_t sB = sA + 16384;

#pragma unroll
        for (int s32 = 0; s32 < 2; s32++) {
            uint32_t bfr[4][4];
#pragma unroll
            for (int nt = 0; nt < 4; nt++) {
                int row = wn * 32 + nt * 8 + brow_l;
                LDMX4(bfr[nt], sB + swz128((uint32_t)(row * 128 + s32 * 64 + bqb_l)));
            }
#pragma unroll
            for (int kh = 0; kh < 2; kh++) {
#pragma unroll
                for (int mt = 0; mt < 4; mt++) {
                    uint32_t afr[4];
                    int row = wm * 64 + mt * 16 + arow_l;
                    LDMX4(afr, sA + swz128((uint32_t)(row * 128 + s32 * 64 + kh * 32 + akb_l)));
#pragma unroll
                    for (int nt = 0; nt < 4; nt++)
                        MMA_F16(acc[mt][nt], afr, &bfr[nt][kh * 2]);
                }
            }
        }
        __syncthreads();
    }

    const int mbase = m0 + wm * 64;
    const int nbase = n0 + wn * 32;
    const int cc = (lane & 3) * 2;
    const int rr = lane >> 2;
    float bx[4], by[4];
#pragma unroll
    for (int nt = 0; nt < 4; nt++) {
        bx[nt] = bias[nbase + nt * 8 + cc];
        by[nt] = bias[nbase + nt * 8 + cc + 1];
    }
#pragma unroll
    for (int mt = 0; mt < 4; mt++) {
        int r0 = mbase + mt * 16 + rr;
#pragma unroll
        for (int nt = 0; nt < 4; nt++) {
            int c0 = nbase + nt * 8 + cc;
            float v0 = acc[mt][nt][0] + bx[nt];
            float v1 = acc[mt][nt][1] + by[nt];
            float v2 = acc[mt][nt][2] + bx[nt];
            float v3 = acc[mt][nt][3] + by[nt];
            if (relu) {
                v0 = fmaxf(v0, 0.f); v1 = fmaxf(v1, 0.f);
                v2 = fmaxf(v2, 0.f); v3 = fmaxf(v3, 0.f);
            }
            if (Ch) {
                *(__half2*)(Ch + (size_t)r0 * N + c0) = __floats2half2_rn(v0, v1);
                *(__half2*)(Ch + (size_t)(r0 + 8) * N + c0) = __floats2half2_rn(v2, v3);
            } else {
                *(float2*)(Cf + (size_t)r0 * N + c0) = make_float2(v0, v1);
                *(float2*)(Cf + (size_t)(r0 + 8) * N + c0) = make_float2(v2, v3);
            }
        }
    }
}

// ========== uproj transposed-output GEMM: g_utr[t][n][b] directly ==========
// Per t: C_t[n, b] = sum_k uT[n,k] * xin[(b,t),k], xin = [xh | st3h] along k.
// A = uT [1024,2048] row-major (M=n). B rows = b: xh/st3h at (b*256+t)*1024.
// grid = (8 m-tiles, 256 t). Epilogue: float2 stores along b into g_utr,
// bias indexed by row (n). Same fragments/swizzle as hgemm_kernel.
__global__ __launch_bounds__(256, 2)
void hgemm_ut_kernel(const __half* __restrict__ W,    // uT
                     const __half* __restrict__ X1,   // xh   (k<1024)
                     const __half* __restrict__ X2,   // st3h (k>=1024)
                     const float* __restrict__ bias)  // U_all_b (per n)
{
    extern __shared__ char smc[];
    const uint32_t sbase = smem_u32(smc);
    const int tid  = threadIdx.x;
    const int wid  = tid >> 5, lane = tid & 31;
    const int m0   = blockIdx.x * 128;   // n-tile
    const int t    = blockIdx.y;
    const int NCH  = 2048 >> 6;          // 32
    const int wm   = wid & 1;
    const int wn   = wid >> 1;

    float acc[4][4][4];
#pragma unroll
    for (int mt = 0; mt < 4; mt++)
#pragma unroll
        for (int nt = 0; nt < 4; nt++)
#pragma unroll
            for (int q = 0; q < 4; q++) acc[mt][nt][q] = 0.f;

    auto load_chunk = [&](int stage, int k0) {
        uint32_t sA = sbase + stage * STG_BYTES;
        uint32_t sB = sA + 16384;
#pragma unroll
        for (int q = 0; q < 4; q++) {
            int v = tid + 256 * q;
            int r = v >> 3, c = (v & 7) << 4;
            CP_ASYNC16(sA + swz128((uint32_t)(r * 128 + c)),
                       (const char*)(W + (size_t)(m0 + r) * 2048 + k0) + c);
        }
        const __half* Xk = (k0 < 1024) ? (X1 + (size_t)t * 1024 + k0)
                                       : (X2 + (size_t)t * 1024 + (k0 - 1024));
#pragma unroll
        for (int q = 0; q < 4; q++) {
            int v = tid + 256 * q;
            int r = v >> 3, c = (v & 7) << 4;   // r = b row
            CP_ASYNC16(sB + swz128((uint32_t)(r * 128 + c)),
                       (const char*)(Xk + (size_t)r * (SEQ * 1024)) + c);
        }
        CP_ASYNC_COMMIT();
    };

    load_chunk(0, 0);
    load_chunk(1, 64);

    const int arow_l = (lane & 15);
    const int akb_l  = (lane >> 4) << 4;
    const int brow_l = (lane & 7);
    const int bqb_l  = (lane >> 3) << 4;

    for (int i = 0; i < NCH; i++) {
        if (i < NCH - 1) { CP_ASYNC_WAIT(1); }
        else             { CP_ASYNC_WAIT(0); }
        __syncthreads();

        const int j = i + STAGES - 1;
        if (j < NCH) load_chunk(j % STAGES, j * 64);

        uint32_t sA = sbase + (i % STAGES) * STG_BYTES;
        uint32_t sB = sA + 16384;

#pragma unroll
        for (int s32 = 0; s32 < 2; s32++) {
            uint32_t bfr[4][4];
#pragma unroll
            for (int nt = 0; nt < 4; nt++) {
                int row = wn * 32 + nt * 8 + brow_l;
                LDMX4(bfr[nt], sB + swz128((uint32_t)(row * 128 + s32 * 64 + bqb_l)));
            }
#pragma unroll
            for (int kh = 0; kh < 2; kh++) {
#pragma unroll
                for (int mt = 0; mt < 4; mt++) {
                    uint32_t afr[4];
                    int row = wm * 64 + mt * 16 + arow_l;
                    LDMX4(afr, sA + swz128((uint32_t)(row * 128 + s32 * 64 + kh * 32 + akb_l)));
#pragma unroll
                    for (int nt = 0; nt < 4; nt++)
                        MMA_F16(acc[mt][nt], afr, &bfr[nt][kh * 2]);
                }
            }
        }
        __syncthreads();
    }

    // epilogue: rows = n, cols = b; bias per row; coalesced float2 along b
    const int mbase = m0 + wm * 64;
    const int nbase = wn * 32;
    const int cc = (lane & 3) * 2;
    const int rr = lane >> 2;
#pragma unroll
    for (int mt = 0; mt < 4; mt++) {
        int r0 = mbase + mt * 16 + rr;
        float bb0 = bias[r0];
        float bb8 = bias[r0 + 8];
        float* row0 = g_utr + ((size_t)t * 1024 + r0) * 128;
        float* row8 = g_utr + ((size_t)t * 1024 + r0 + 8) * 128;
#pragma unroll
        for (int nt = 0; nt < 4; nt++) {
            int c0 = nbase + nt * 8 + cc;
            *(float2*)(row0 + c0) = make_float2(acc[mt][nt][0] + bb0,
                                                acc[mt][nt][1] + bb0);
            *(float2*)(row8 + c0) = make_float2(acc[mt][nt][2] + bb8,
                                                acc[mt][nt][3] + bb8);
        }
    }
}

// ---------------- weight transposes (fp16 out) + barrier init --------------
__global__ void wtrans_kernel(const float* __restrict__ w2,
                              const float* __restrict__ w3,
                              const float* __restrict__ uw,
                              const float* __restrict__ w1)
{
    if (blockIdx.x == 0 && blockIdx.y == 0 && blockIdx.z == 0 &&
        threadIdx.x == 0 && threadIdx.y == 0) {
        g_bar_count = 0u;
        g_bar_gen = 0u;
    }
    __shared__ float t[32][33];
    const int tx = threadIdx.x, ty = threadIdx.y;

    if (blockIdx.z == 3) {
        if ((int)blockIdx.x * 32 >= 256 || (int)blockIdx.y * 32 >= 128) return;
#pragma unroll
        for (int i = 0; i < 4; i++) {
            int r = blockIdx.y * 32 + ty + i * 8;
            int c = blockIdx.x * 32 + tx;
            t[ty + i * 8][tx] = (r < 67) ? w1[(size_t)r * 256 + c] : 0.f;
        }
        __syncthreads();
#pragma unroll
        for (int i = 0; i < 4; i++) {
            int c = blockIdx.x * 32 + ty + i * 8;
            int r = blockIdx.y * 32 + tx;
            g_w1t[(size_t)c * 128 + r] = __float2half_rn(t[tx][ty + i * 8]);
        }
        return;
    }

    const float* in; __half* out; int R, C;
    if (blockIdx.z == 0)      { in = w2; out = g_w2t; R = 256;  C = 512;  }
    else if (blockIdx.z == 1) { in = w3; out = g_w3t; R = 512;  C = 1024; }
    else                      { in = uw; out = g_uT;  R = 2048; C = 1024; }
    if ((int)blockIdx.x * 32 >= C || (int)blockIdx.y * 32 >= R) return;
#pragma unroll
    for (int i = 0; i < 4; i++) {
        int r = blockIdx.y * 32 + ty + i * 8;
        int c = blockIdx.x * 32 + tx;
        t[ty + i * 8][tx] = in[(size_t)r * C + c];
    }
    __syncthreads();
#pragma unroll
    for (int i = 0; i < 4; i++) {
        int c = blockIdx.x * 32 + ty + i * 8;
        int r = blockIdx.y * 32 + tx;
        out[(size_t)c * R + r] = __float2half_rn(t[tx][ty + i * 8]);
    }
}

// ---------------- input conversions ----------------------------------------
__global__ void convx_kernel(const float* __restrict__ x)
{
    size_t i = ((size_t)blockIdx.x * 512 + threadIdx.x) * 4;
    float4 v = *(const float4*)(x + i);
    *(__half2*)(&g_xh[i])     = __floats2half2_rn(v.x, v.y);
    *(__half2*)(&g_xh[i + 2]) = __floats2half2_rn(v.z, v.w);
}
__global__ void convs_kernel(const float* __restrict__ s)
{
    int idx = blockIdx.x * 256 + threadIdx.x;
    int m = idx >> 7, k = idx & 127;
    float v = (k < 67) ? s[(size_t)m * 67 + k] : 0.f;
    g_sth[idx] = __float2half_rn(v);
}

__device__ __forceinline__ void grid_barrier(unsigned gen)
{
    __syncthreads();
    if (threadIdx.x == 0) {
        __threadfence();
        unsigned arrived = atomicAdd(&g_bar_count, 1u) + 1u;
        if (arrived == gen * SC2_NBLK) {
            __threadfence();
            *(volatile unsigned*)&g_bar_gen = gen;
        } else {
            while (*(volatile unsigned*)&g_bar_gen < gen) { __nanosleep(32); }
        }
        __threadfence();
    }
    __syncthreads();
}

__device__ __forceinline__ float sigf(float x) { return 1.f / (1.f + __expf(-x)); }

// ================= persistent TLSTM scan (R15 core, no transpose) ==========
#define S2_WOFF 0                 // Wsm2: uint64 [256*4*5]   = 40960 B
#define S2_POFF 40960             // P:    float  [16*4*5*64] = 81920 B
#define S2_BOFF 122880            // Bi:   float  [20]
#define S2_SMEM 123008

__global__ __launch_bounds__(512, 1) void scan2_kernel(
    const float* __restrict__ ts,
    const float* __restrict__ W_all, const float* __restrict__ W_all_b,
    const float* __restrict__ W_d,   const float* __restrict__ W_d_b,
    float* __restrict__ feat)
{
    extern __shared__ char smc[];
    uint64_t* Wsm = (uint64_t*)(smc + S2_WOFF);
    float*    P   = (float*)(smc + S2_POFF);
    float*    Bi  = (float*)(smc + S2_BOFF);

    const int tid    = threadIdx.x;
    const int bh     = blockIdx.x & 1;
    const int j0     = (blockIdx.x >> 1) * 4;
    const int b_base = bh * 64;

    // ---- stage weights (once), duplicated into f32x2 pairs ----
    for (int idx = tid; idx < 5120; idx += 512) {
        int k = idx / 20, r = idx % 20;
        int j = r / 5, g = r % 5;
        float v = (g < 4) ? W_all[k * 1024 + g * 256 + j0 + j]
                          : W_d[k * 256 + j0 + j];
        Wsm[(k * 4 + j) * 5 + g] = pk2(v, v);
    }
    if (tid < 20) {
        int j = tid / 5, g = tid % 5;
        Bi[tid] = (g < 4) ? W_all_b[g * 256 + j0 + j] : W_d_b[j0 + j];
    }
    // zero h0/c0 (parity-0 buffers)
    {
        float* hc0 = &g_hc[0][0][0];
        for (int idx = blockIdx.x * 512 + tid; idx < 2 * HID * BATCH;
             idx += SC2_NBLK * 512)
            hc0[idx] = 0.f;
    }
    grid_barrier(1);

    const int warp = tid >> 5, lane = tid & 31;
    const int jp = lane >> 4;
    const int bq = lane & 15;
    const int b  = b_base + bq * 4;
    const int kbeg = warp * 16;
    const int rjj = tid >> 6, rbl = tid & 63;          // reduction role
    const int rjg = j0 + rjj, rbg = b_base + rbl;

    for (int t = 0; t < SEQ; t++) {
        const float* hT = &g_hc[t & 1][0][0];
        const float* cT = &g_hc[t & 1][1][0];

        // prefetch pointwise operands (independent of h/c) — overlaps FMA
        float pu0 = 0.f, pu1 = 0.f, pu2 = 0.f, pu3 = 0.f, ptt = 0.f, pcp = 0.f;
        if (tid < 256) {
            const float* up = g_utr + ((size_t)t * 1024 + rjg) * 128 + rbg;
            pu0 = __ldg(up + 0 * 256 * 128);
            pu1 = __ldg(up + 1 * 256 * 128);
            pu2 = __ldg(up + 2 * 256 * 128);
            pu3 = __ldg(up + 3 * 256 * 128);
            ptt = __ldg(ts + rbg * SEQ + t);
            pcp = cT[rjg * 128 + rbg];
        }

        uint64_t acc2[2][5][2];
#pragma unroll
        for (int jj = 0; jj < 2; jj++)
#pragma unroll
            for (int g = 0; g < 5; g++) {
                acc2[jj][g][0] = 0ull;
                acc2[jj][g][1] = 0ull;
            }

#pragma unroll 8
        for (int kk = 0; kk < 16; kk++) {
            int k = kbeg + kk;
            float4 h4 = *(const float4*)(hT + k * 128 + b);
            float4 c4 = *(const float4*)(cT + k * 128 + b);
            uint64_t hp0 = pk2(h4.x, h4.y), hp1 = pk2(h4.z, h4.w);
            uint64_t cp0 = pk2(c4.x, c4.y), cp1 = pk2(c4.z, c4.w);
#pragma unroll
            for (int jj = 0; jj < 2; jj++) {
                const uint64_t* wr = Wsm + ((size_t)(k * 4 + jp * 2 + jj)) * 5;
                uint64_t w0 = wr[0], w1 = wr[1], w2 = wr[2], w3 = wr[3], w4 = wr[4];
                acc2[jj][0][0] = ffma2(hp0, w0, acc2[jj][0][0]);
                acc2[jj][0][1] = ffma2(hp1, w0, acc2[jj][0][1]);
                acc2[jj][1][0] = ffma2(hp0, w1, acc2[jj][1][0]);
                acc2[jj][1][1] = ffma2(hp1, w1, acc2[jj][1][1]);
                acc2[jj][2][0] = ffma2(hp0, w2, acc2[jj][2][0]);
                acc2[jj][2][1] = ffma2(hp1, w2, acc2[jj][2][1]);
                acc2[jj][3][0] = ffma2(hp0, w3, acc2[jj][3][0]);
                acc2[jj][3][1] = ffma2(hp1, w3, acc2[jj][3][1]);
                acc2[jj][4][0] = ffma2(cp0, w4, acc2[jj][4][0]);
                acc2[jj][4][1] = ffma2(cp1, w4, acc2[jj][4][1]);
            }
        }

#pragma unroll
        for (int jj = 0; jj < 2; jj++)
#pragma unroll
            for (int g = 0; g < 5; g++) {
                float2 lo = upk2(acc2[jj][g][0]);
                float2 hi = upk2(acc2[jj][g][1]);
                *(float4*)&P[((warp * 4 + jp * 2 + jj) * 5 + g) * 64 + bq * 4] =
                    make_float4(lo.x, lo.y, hi.x, hi.y);
            }
        __syncthreads();

        if (tid < 256) {
            float s[5];
#pragma unroll
            for (int g = 0; g < 5; g++) s[g] = Bi[rjj * 5 + g];
#pragma unroll
            for (int q = 0; q < 16; q++) {
#pragma unroll
                for (int g = 0; g < 5; g++)
                    s[g] += P[((q * 4 + rjj) * 5 + g) * 64 + rbl];
            }
            float f  = sigf(s[0] + pu0);
            float ii = sigf(s[1] + pu1);
            float o  = sigf(s[2] + pu2);
            float ct = sigf(s[3] + pu3);
            float d  = tanhf(s[4]);
            float c_adj = (pcp - d) + d * ptt;
            float cn = f * c_adj + ii * ct;
            float hn = o * tanhf(cn);
            g_hc[(t + 1) & 1][0][rjg * 128 + rbg] = hn;
            g_hc[(t + 1) & 1][1][rjg * 128 + rbg] = cn;
            feat[((size_t)rbg * SEQ + t) * HID + rjg] = hn;
        }
        grid_barrier((unsigned)(t + 2));
    }
}

// ---------------- classifier ----------------------------------------------
__global__ void cls_kernel(const float* __restrict__ feat,
                           const float* __restrict__ w,
                           const float* __restrict__ bias,
                           float* __restrict__ out)
{
    int lane = threadIdx.x & 31;
    int wrow = (blockIdx.x * blockDim.x + threadIdx.x) >> 5;
    if (wrow >= MROWS) return;
    const float* fr = feat + (size_t)wrow * HID;
    float s = 0.f;
#pragma unroll
    for (int i = 0; i < 8; i++) s += fr[lane + 32 * i] * w[lane + 32 * i];
#pragma unroll
    for (int off = 16; off > 0; off >>= 1)
        s += __shfl_down_sync(0xffffffffu, s, off);
    if (lane == 0) out[wrow] = s + bias[0];
}

// ---------------------------------------------------------------------------
extern "C" void kernel_launch(void* const* d_in, const int* in_sizes, int n_in,
                              void* d_out, int out_size)
{
    const float* x       = (const float*)d_in[0];
    const float* stages  = (const float*)d_in[1];
    const float* tsmp    = (const float*)d_in[2];
    const float* se_w1   = (const float*)d_in[3];
    const float* se_b1   = (const float*)d_in[4];
    const float* se_w2   = (const float*)d_in[5];
    const float* se_b2   = (const float*)d_in[6];
    const float* se_w3   = (const float*)d_in[7];
    const float* se_b3   = (const float*)d_in[8];
    const float* W_all_w = (const float*)d_in[9];
    const float* W_all_b = (const float*)d_in[10];
    const float* U_all_w = (const float*)d_in[11];
    const float* U_all_b = (const float*)d_in[12];
    const float* W_d_w   = (const float*)d_in[13];
    const float* W_d_b   = (const float*)d_in[14];
    const float* cls_w   = (const float*)d_in[15];
    const float* cls_b   = (const float*)d_in[16];

    float* out  = (float*)d_out;
    float* feat = out + MROWS;

    void *p_sth, *p_st1, *p_st2, *p_st3, *p_w1t, *p_w2t, *p_w3t, *p_uT, *p_xh;
    cudaGetSymbolAddress(&p_sth, g_sth);
    cudaGetSymbolAddress(&p_st1, g_st1h);
    cudaGetSymbolAddress(&p_st2, g_st2h);
    cudaGetSymbolAddress(&p_st3, g_st3h);
    cudaGetSymbolAddress(&p_w1t, g_w1t);
    cudaGetSymbolAddress(&p_w2t, g_w2t);
    cudaGetSymbolAddress(&p_w3t, g_w3t);
    cudaGetSymbolAddress(&p_uT,  g_uT);
    cudaGetSymbolAddress(&p_xh,  g_xh);
    __half* sth  = (__half*)p_sth;
    __half* st1h = (__half*)p_st1;
    __half* st2h = (__half*)p_st2;
    __half* st3h = (__half*)p_st3;
    __half* w1t  = (__half*)p_w1t;
    __half* w2t  = (__half*)p_w2t;
    __half* w3t  = (__half*)p_w3t;
    __half* uT   = (__half*)p_uT;
    __half* xh   = (__half*)p_xh;

    cudaFuncSetAttribute(hgemm_kernel,
                         cudaFuncAttributeMaxDynamicSharedMemorySize, HG_SMEM);
    cudaFuncSetAttribute(hgemm_ut_kernel,
                         cudaFuncAttributeMaxDynamicSharedMemorySize, HG_SMEM);
    cudaFuncSetAttribute(scan2_kernel,
                         cudaFuncAttributeMaxDynamicSharedMemorySize, S2_SMEM);

    // 1. weight transposes (fp16) + barrier init
    wtrans_kernel<<<dim3(32, 64, 4), dim3(32, 8)>>>(se_w2, se_w3, U_all_w, se_w1);
    // 2. x/stages -> fp16
    convx_kernel<<<16384, 512>>>(x);
    convs_kernel<<<16384, 256>>>(stages);
    // 3. se1: fp16 mma, K=128 (padded)
    hgemm_kernel<<<dim3(2, 256), 256, HG_SMEM>>>(
        sth, 128, sth, 128, w1t, se_b1, nullptr, st1h, MROWS, 256, 128, 1);
    // 4. se2: K=256
    hgemm_kernel<<<dim3(4, 256), 256, HG_SMEM>>>(
        st1h, 256, st1h, 256, w2t, se_b2, nullptr, st2h, MROWS, 512, 256, 1);
    // 5. se3: K=512
    hgemm_kernel<<<dim3(8, 256), 256, HG_SMEM>>>(
        st2h, 512, st2h, 512, w3t, se_b3, nullptr, st3h, MROWS, 1024, 512, 1);
    // 6. uproj transposed-output: writes g_utr[t][n][b] directly (no g_u,
    //    no transpose pass)
    hgemm_ut_kernel<<<dim3(8, 256), 256, HG_SMEM>>>(uT, xh, st3h, U_all_b);
    // 7. persistent scan (no transpose prologue)
    scan2_kernel<<<SC2_NBLK, 512, S2_SMEM>>>(tsmp, W_all_w, W_all_b,
                                             W_d_w, W_d_b, feat);
    // 8. classifier
    cls_kernel<<<4096, 256>>>(feat, cls_w, cls_b, out);
}